// round 16
// baseline (speedup 1.0000x reference)
#include <cuda_runtime.h>
#include <cuda_bf16.h>

// Problem shapes (fixed by the dataset)
#define B_   128
#define P_   4096
#define L_   128
#define TPB  64
#define PPT  8                          // proposals per thread (ILP depth)
#define BLOCKS_PER_B (P_ / (TPB * PPT)) // 8
#define NB   (B_ * BLOCKS_PER_B)        // 1024 partials

__device__ float        g_partials[NB];
__device__ unsigned int g_count = 0;

__device__ __forceinline__ float huber1(float e) {
    float a = fabsf(e);
    return (a <= 1.0f) ? 0.5f * e * e : a - 0.5f;
}

__global__ __launch_bounds__(TPB)
void classifier_loss_kernel(const float* __restrict__ cls,
                            const float* __restrict__ deltas,
                            const float* __restrict__ roi,
                            const float* __restrict__ labels,
                            const int*   __restrict__ neg_flag,
                            float*       __restrict__ out)
{
    __shared__ float4 s_box[L_];   // lx, ly, lx+lw, ly+lh
    __shared__ float  s_la[L_];    // lw*lh
    __shared__ float2 s_wh[L_];    // lw, lh (exact, for targets)
    __shared__ float  s_red[TPB];
    __shared__ bool   s_last;
    __shared__ double s_d[TPB];

    const int tid = threadIdx.x;
    const int b   = blockIdx.y;
    const int pb  = blockIdx.x * (TPB * PPT) + tid;   // proposal base

    // Stage labels: 64 threads load 2 labels each
#pragma unroll
    for (int k = 0; k < L_ / TPB; ++k) {
        int i = tid + k * TPB;
        float4 v = ((const float4*)(labels + (size_t)b * L_ * 4))[i];
        s_box[i] = make_float4(v.x, v.y, v.x + v.z, v.y + v.w);
        s_la[i]  = v.z * v.w;
        s_wh[i]  = make_float2(v.z, v.w);
    }
    __syncthreads();

    // Per-proposal state (SCALE=32 is an exact pow2 multiply)
    float rx[PPT], ry[PPT], rx2[PPT], ry2[PPT], rA[PPT];
    int best[PPT];
#pragma unroll
    for (int q = 0; q < PPT; ++q) {
        float4 r = ((const float4*)(roi + (size_t)b * P_ * 4))[pb + q * TPB];
        float x = r.x * 32.0f, y = r.y * 32.0f, w = r.z * 32.0f, h = r.w * 32.0f;
        rx[q] = x; ry[q] = y; rx2[q] = x + w; ry2[q] = y + h;
        rA[q] = w * h;
        best[q] = (int)0x80000000;   // INT_MIN: loses to every packed score
    }

    // argmax_l of iou == argmax_l of inter/(la + rA)  (monotone transform;
    // union = la + rA - inter, and x -> x/(1+x) is monotone).
    // Single-clamp trick: sc = dx * max(dy,0) / (la+rA):
    //   dy<0 -> sc = +/-0 ; dx<0,dy>=0 -> sc<0 ; overlap -> sc>0 correct.
    // Signed packed argmax: high 25 bits = score bits, low 7 bits = 127-l;
    // for positive scores int order == float order, and the tag gives the
    // FIRST max index on ties (matches jnp.argmax). pos <=> (best&~0x7F) > 0.
    // 8 independent streams per thread bury LDS/MUFU latency in-thread.
#pragma unroll 4
    for (int l = 0; l < L_; ++l) {
        float4 lb = s_box[l];
        float  la = s_la[l];
        int tag = 127 - l;
#pragma unroll
        for (int q = 0; q < PPT; ++q) {
            float dx = fminf(lb.z, rx2[q]) - fmaxf(lb.x, rx[q]);
            float dy = fminf(lb.w, ry2[q]) - fmaxf(lb.y, ry[q]);
            float sy = fmaxf(dy, 0.0f);
            float sc = __fdividef(dx * sy, la + rA[q]);
            int pk = (int)((__float_as_uint(sc) & 0xFFFFFF80u) | (unsigned)tag);
            best[q] = max(best[q], pk);                      // signed IMNMX
        }
    }

    const int neg = __ldg(neg_flag);
    const float LOG01 = -2.3025850929940457f;   // log(0.1)
    const float LOG09 = -0.10536051565782628f;  // log(0.9)
    const float* cb = cls    + (size_t)b * 2 * P_;
    const float* db = deltas + (size_t)b * 4 * P_;

    float per_sum = 0.0f;

#pragma unroll
    for (int q = 0; q < PPT; ++q) {
        const int p  = pb + q * TPB;
        const int be = best[q];

        int  bidx = 127 - (be & 0x7F);
        bool pos  = ((be & (int)0xFFFFFF80) > 0) && (bidx > 0);

        float l0 = cb[p];
        float l1 = cb[P_ + p];
        float mx = fmaxf(l0, l1);
        float e0 = __expf(l0 - mx);
        float e1 = __expf(l1 - mx);
        float inv = __fdividef(1.0f, e0 + e1);
        float pr0 = e0 * inv, pr1 = e1 * inv;

        float per;
        if (pos) {
            float ce_pos = -(pr0 * LOG01 + pr1 * LOG09);
            float4 mb  = s_box[bidx];
            float2 mwh = s_wh[bidx];
            float rw = rx2[q] - rx[q];          // ~1 ulp vs exact rw; fine
            float rh = ry2[q] - ry[q];
            float invw = __fdividef(1.0f, rw);
            float invh = __fdividef(1.0f, rh);
            float tx = (mb.x - rx[q]) * invw;
            float ty = (mb.y - ry[q]) * invh;
            float tw = __logf(fmaxf(mwh.x * invw, 1e-8f));
            float th = __logf(fmaxf(mwh.y * invh, 1e-8f));
            float hx = huber1(tx - db[p]);
            float hy = huber1(ty - db[P_ + p]);
            float hw = huber1(tw - db[2 * P_ + p]);
            float hh = huber1(th - db[3 * P_ + p]);
            per = 0.5f * (hx + hy + hw + hh) + ce_pos;   // 2 * mean(huber)
        } else {
            float ce_neg = -(pr0 * LOG09 + pr1 * LOG01);
            per = (neg > 0) ? ce_neg : 0.0f;
        }
        per_sum += per;
    }

    // Deterministic block reduction
    s_red[tid] = per_sum;
    __syncthreads();
#pragma unroll
    for (int s = TPB / 2; s > 0; s >>= 1) {
        if (tid < s) s_red[tid] += s_red[tid + s];
        __syncthreads();
    }

    if (tid == 0) {
        g_partials[b * BLOCKS_PER_B + blockIdx.x] = s_red[0];
        __threadfence();
        unsigned t = atomicAdd(&g_count, 1u);
        s_last = (t == NB - 1);
    }
    __syncthreads();

    // Last block does the fixed-order final reduction (deterministic:
    // identical summation order regardless of which block is last).
    if (s_last) {
        double acc = 0.0;
#pragma unroll
        for (int i = tid; i < NB; i += TPB)
            acc += (double)__ldcg(&g_partials[i]);
        s_d[tid] = acc;
        __syncthreads();
#pragma unroll
        for (int st = TPB / 2; st > 0; st >>= 1) {
            if (tid < st) s_d[tid] += s_d[tid + st];
            __syncthreads();
        }
        if (tid == 0) {
            out[0]  = (float)s_d[0];
            g_count = 0;   // reset for next graph replay
        }
    }
}

extern "C" void kernel_launch(void* const* d_in, const int* in_sizes, int n_in,
                              void* d_out, int out_size)
{
    const float* cls    = (const float*)d_in[0];  // [B, 2P]
    const float* deltas = (const float*)d_in[1];  // [B, 4P]
    const float* roi    = (const float*)d_in[2];  // [B, P, 4]
    const float* labels = (const float*)d_in[3];  // [B, L, 4]
    const int*   negf   = (const int*)  d_in[4];  // scalar

    dim3 grid(BLOCKS_PER_B, B_);
    classifier_loss_kernel<<<grid, TPB>>>(cls, deltas, roi, labels, negf,
                                          (float*)d_out);
    (void)in_sizes; (void)n_in; (void)out_size;
}

// round 17
// speedup vs baseline: 1.1991x; 1.1991x over previous
#include <cuda_runtime.h>
#include <cuda_bf16.h>

// Problem shapes (fixed by the dataset)
#define B_   128
#define P_   4096
#define L_   128
#define TPB  128
#define PPT  4                          // proposals per thread
#define BLOCKS_PER_B (P_ / (TPB * PPT)) // 8
#define NB   (B_ * BLOCKS_PER_B)        // 1024 partials

__device__ float        g_partials[NB];
__device__ unsigned int g_count = 0;

__device__ __forceinline__ float huber1(float e) {
    float a = fabsf(e);
    return (a <= 1.0f) ? 0.5f * e * e : a - 0.5f;
}

__global__ __launch_bounds__(TPB)
void classifier_loss_kernel(const float* __restrict__ cls,
                            const float* __restrict__ deltas,
                            const float* __restrict__ roi,
                            const float* __restrict__ labels,
                            const int*   __restrict__ neg_flag,
                            float*       __restrict__ out)
{
    __shared__ float4 s_box[L_];   // lx, ly, lx+lw, ly+lh
    __shared__ float  s_la[L_];    // lw*lh
    __shared__ float2 s_wh[L_];    // lw, lh (exact, for targets)
    __shared__ float  s_red[TPB];
    __shared__ bool   s_last;
    __shared__ double s_d[TPB];

    const int tid = threadIdx.x;
    const int b   = blockIdx.y;
    const int pb  = blockIdx.x * (TPB * PPT) + tid;   // proposal base

    if (tid < L_) {
        float4 v = ((const float4*)(labels + (size_t)b * L_ * 4))[tid];
        s_box[tid] = make_float4(v.x, v.y, v.x + v.z, v.y + v.w);
        s_la[tid]  = v.z * v.w;
        s_wh[tid]  = make_float2(v.z, v.w);
    }
    __syncthreads();

    const float* cb = cls + (size_t)b * 2 * P_;

    // Per-proposal state (SCALE=32 is an exact pow2 multiply).
    // Prefetch the classifier logits NOW so their DRAM/L2 latency is hidden
    // under the ~13K-cycle label loop instead of being exposed in the tail.
    float rx[PPT], ry[PPT], rx2[PPT], ry2[PPT], rA[PPT];
    float l0p[PPT], l1p[PPT];
    int best[PPT];
#pragma unroll
    for (int q = 0; q < PPT; ++q) {
        float4 r = ((const float4*)(roi + (size_t)b * P_ * 4))[pb + q * TPB];
        float x = r.x * 32.0f, y = r.y * 32.0f, w = r.z * 32.0f, h = r.w * 32.0f;
        rx[q] = x; ry[q] = y; rx2[q] = x + w; ry2[q] = y + h;
        rA[q] = w * h;
        best[q] = (int)0x80000000;   // INT_MIN: loses to every packed score
        l0p[q] = __ldg(cb + pb + q * TPB);
        l1p[q] = __ldg(cb + P_ + pb + q * TPB);
    }

    // argmax_l of iou == argmax_l of inter/(la + rA)  (monotone transform;
    // union = la + rA - inter, and x -> x/(1+x) is monotone).
    // Single-clamp trick: sc = dx * max(dy,0) / (la+rA):
    //   dy<0 -> sc = +/-0 ; dx<0,dy>=0 -> sc<0 ; overlap -> sc>0 correct.
    // Signed packed argmax: high 25 bits = score bits, low 7 bits = 127-l;
    // for positive scores int order == float order, and the tag gives the
    // FIRST max index on ties (matches jnp.argmax). pos <=> (best&~0x7F) > 0.
    // NOTE: no inline asm anywhere in this loop — ptxas owns scheduling.
#pragma unroll 8
    for (int l = 0; l < L_; ++l) {
        float4 lb = s_box[l];
        float  la = s_la[l];
        int tag = 127 - l;
#pragma unroll
        for (int q = 0; q < PPT; ++q) {
            float dx = fminf(lb.z, rx2[q]) - fmaxf(lb.x, rx[q]);
            float dy = fminf(lb.w, ry2[q]) - fmaxf(lb.y, ry[q]);
            float sy = fmaxf(dy, 0.0f);
            float sc = __fdividef(dx * sy, la + rA[q]);
            int pk = (int)((__float_as_uint(sc) & 0xFFFFFF80u) | (unsigned)tag);
            best[q] = max(best[q], pk);                      // signed IMNMX
        }
    }

    const int neg = __ldg(neg_flag);
    const float LOG01 = -2.3025850929940457f;   // log(0.1)
    const float LOG09 = -0.10536051565782628f;  // log(0.9)
    const float* db = deltas + (size_t)b * 4 * P_;

    float per_sum = 0.0f;

#pragma unroll
    for (int q = 0; q < PPT; ++q) {
        const int p  = pb + q * TPB;
        const int be = best[q];

        int  bidx = 127 - (be & 0x7F);
        bool pos  = ((be & (int)0xFFFFFF80) > 0) && (bidx > 0);

        float l0 = l0p[q];
        float l1 = l1p[q];
        float mx = fmaxf(l0, l1);
        float e0 = __expf(l0 - mx);
        float e1 = __expf(l1 - mx);
        float inv = __fdividef(1.0f, e0 + e1);
        float pr0 = e0 * inv, pr1 = e1 * inv;

        float per;
        if (pos) {
            float ce_pos = -(pr0 * LOG01 + pr1 * LOG09);
            float4 mb  = s_box[bidx];
            float2 mwh = s_wh[bidx];
            float rw = rx2[q] - rx[q];          // ~1 ulp vs exact rw; fine
            float rh = ry2[q] - ry[q];
            float invw = __fdividef(1.0f, rw);
            float invh = __fdividef(1.0f, rh);
            float tx = (mb.x - rx[q]) * invw;
            float ty = (mb.y - ry[q]) * invh;
            float tw = __logf(fmaxf(mwh.x * invw, 1e-8f));
            float th = __logf(fmaxf(mwh.y * invh, 1e-8f));
            float hx = huber1(tx - db[p]);
            float hy = huber1(ty - db[P_ + p]);
            float hw = huber1(tw - db[2 * P_ + p]);
            float hh = huber1(th - db[3 * P_ + p]);
            per = 0.5f * (hx + hy + hw + hh) + ce_pos;   // 2 * mean(huber)
        } else {
            float ce_neg = -(pr0 * LOG09 + pr1 * LOG01);
            per = (neg > 0) ? ce_neg : 0.0f;
        }
        per_sum += per;
    }

    // Deterministic block reduction
    s_red[tid] = per_sum;
    __syncthreads();
#pragma unroll
    for (int s = TPB / 2; s > 0; s >>= 1) {
        if (tid < s) s_red[tid] += s_red[tid + s];
        __syncthreads();
    }

    if (tid == 0) {
        g_partials[b * BLOCKS_PER_B + blockIdx.x] = s_red[0];
        __threadfence();
        unsigned t = atomicAdd(&g_count, 1u);
        s_last = (t == NB - 1);
    }
    __syncthreads();

    // Last block does the fixed-order final reduction (deterministic:
    // identical summation order regardless of which block is last).
    if (s_last) {
        double acc = 0.0;
#pragma unroll
        for (int i = tid; i < NB; i += TPB)
            acc += (double)__ldcg(&g_partials[i]);
        s_d[tid] = acc;
        __syncthreads();
#pragma unroll
        for (int st = TPB / 2; st > 0; st >>= 1) {
            if (tid < st) s_d[tid] += s_d[tid + st];
            __syncthreads();
        }
        if (tid == 0) {
            out[0]  = (float)s_d[0];
            g_count = 0;   // reset for next graph replay
        }
    }
}

extern "C" void kernel_launch(void* const* d_in, const int* in_sizes, int n_in,
                              void* d_out, int out_size)
{
    const float* cls    = (const float*)d_in[0];  // [B, 2P]
    const float* deltas = (const float*)d_in[1];  // [B, 4P]
    const float* roi    = (const float*)d_in[2];  // [B, P, 4]
    const float* labels = (const float*)d_in[3];  // [B, L, 4]
    const int*   negf   = (const int*)  d_in[4];  // scalar

    dim3 grid(BLOCKS_PER_B, B_);
    classifier_loss_kernel<<<grid, TPB>>>(cls, deltas, roi, labels, negf,
                                          (float*)d_out);
    (void)in_sizes; (void)n_in; (void)out_size;
}